// round 11
// baseline (speedup 1.0000x reference)
#include <cuda_runtime.h>
#include <cuda_bf16.h>
#include <math.h>

// ---------------- problem constants ----------------
#define Bn    2
#define Nn    2048
#define DIMn  512
#define Hn    4
#define DHn   128
#define CH    64
#define NCn   32
#define BHn   8
#define Pn    256            // BH * NC
#define DHIDn 512
#define ROWS  (Bn*Nn)        // 4096 tokens
#define KROWS (Pn*CH)        // 16384 chunk-major rows

// ---------------- static scratch (no cudaMalloc allowed) ----------------
__device__ float g_xs[ROWS*DIMn];
__device__ float g_xr[ROWS*DIMn];
__device__ float g_q [KROWS*DHn];
__device__ float g_k [KROWS*DHn];
__device__ float g_v [KROWS*DHn];
__device__ float g_u [KROWS*DHn];
__device__ float g_h [KROWS*DHn];
__device__ float g_hq[KROWS*DHn];
__device__ float g_lr[KROWS];
__device__ float g_gate[ROWS*Hn];
__device__ float g_beta [NCn*BHn];
__device__ float g_alpha[NCn*BHn];
__device__ float g_z1 [KROWS*DHIDn];
__device__ float g_a1 [KROWS*DHIDn];
__device__ float g_dz1[KROWS*DHIDn];
__device__ float g_dpred[KROWS*DHn];
__device__ float g_dh  [KROWS*DHn];
__device__ float g_gg [Pn*DHn];
__device__ float g_gw1[Pn*DHn*DHIDn];
__device__ float g_gw2[Pn*DHIDn*DHn];
__device__ float g_gp [Pn*DHn];
__device__ float g_w1p[(size_t)Pn*DHn*DHIDn];
__device__ float g_w2p[(size_t)Pn*DHIDn*DHn];
__device__ float g_ret[ROWS*DIMn];

// ---------------- small helpers ----------------
__device__ __forceinline__ float sigm(float x) { return 1.0f / (1.0f + expf(-x)); }
__device__ __forceinline__ float gelu_f(float x) {
    return 0.5f * x * (1.0f + erff(x * 0.70710678118654752f));
}
__device__ __forceinline__ float gelu_grad_f(float x) {
    float c = 0.5f * (1.0f + erff(x * 0.70710678118654752f));
    return c + x * 0.3989422804014327f * expf(-0.5f * x * x);
}

__device__ __forceinline__ unsigned s2u(const void* p) {
    return (unsigned)__cvta_generic_to_shared(p);
}
__device__ __forceinline__ void cpa16(unsigned d, const void* s) {
    asm volatile("cp.async.cg.shared.global [%0], [%1], 16;" :: "r"(d), "l"(s));
}
__device__ __forceinline__ void cpa4(unsigned d, const void* s) {
    asm volatile("cp.async.ca.shared.global [%0], [%1], 4;" :: "r"(d), "l"(s));
}
#define CP_COMMIT() asm volatile("cp.async.commit_group;" ::: "memory")

template<int NT>
__device__ __forceinline__ float blk_sum(float v) {
    __shared__ float sbuf[NT/32];
    int tid = threadIdx.x;
    #pragma unroll
    for (int o = 16; o > 0; o >>= 1) v += __shfl_xor_sync(0xffffffffu, v, o);
    if ((tid & 31) == 0) sbuf[tid >> 5] = v;
    __syncthreads();
    float s = (tid < NT/32) ? sbuf[tid] : 0.0f;
    if (tid < 32) {
        #pragma unroll
        for (int o = NT/64; o > 0; o >>= 1) s += __shfl_xor_sync(0xffffffffu, s, o);
        if (tid == 0) sbuf[0] = s;
    }
    __syncthreads();
    s = sbuf[0];
    __syncthreads();
    return s;
}

// epilogue shared by gemm kernels: one float4 quad
template<int EPI>
__device__ __forceinline__ void epi_store(float* __restrict__ C, int ldc, int p,
                                          int m, int n, float4 v)
{
    if (EPI == 0) {                      // plain
        *reinterpret_cast<float4*>(&C[(size_t)m * ldc + n]) = v;
    } else if (EPI == 1) {               // qkv remap token->chunk (quad stays in-head)
        int b = m >> 11, tt = m & 2047, c = tt >> 6, ii = tt & 63;
        int h = n >> 7, d = n & 127;
        size_t o = ((size_t)((b * 4 + h) * 32 + c)) * (64 * 128) + ii * 128 + d;
        *reinterpret_cast<float4*>(&C[o]) = v;
    } else if (EPI == 2) {               // z1 + gelu -> a1
        size_t o = (size_t)m * 512 + n;
        *reinterpret_cast<float4*>(&C[o]) = v;
        float4 g = make_float4(gelu_f(v.x), gelu_f(v.y), gelu_f(v.z), gelu_f(v.w));
        *reinterpret_cast<float4*>(&g_a1[o]) = g;
    } else if (EPI == 3) {               // dpred = 2*lr/DH * (z2 + k - v)
        size_t o = (size_t)m * 128 + n;
        float4 kk4 = *reinterpret_cast<const float4*>(&g_k[o]);
        float4 vv4 = *reinterpret_cast<const float4*>(&g_v[o]);
        float s = g_lr[m] * (2.0f / 128.0f);
        float4 r = make_float4((v.x + kk4.x - vv4.x) * s, (v.y + kk4.y - vv4.y) * s,
                               (v.z + kk4.z - vv4.z) * s, (v.w + kk4.w - vv4.w) * s);
        *reinterpret_cast<float4*>(&C[o]) = r;
    } else if (EPI == 4) {               // dz1 = da1 * gelu'(z1)
        size_t o = (size_t)m * 512 + n;
        float4 z4 = *reinterpret_cast<const float4*>(&g_z1[o]);
        float4 r = make_float4(v.x * gelu_grad_f(z4.x), v.y * gelu_grad_f(z4.y),
                               v.z * gelu_grad_f(z4.z), v.w * gelu_grad_f(z4.w));
        *reinterpret_cast<float4*>(&C[o]) = r;
    } else if (EPI == 5) {               // a1r = gelu(z1r)
        float4 g = make_float4(gelu_f(v.x), gelu_f(v.y), gelu_f(v.z), gelu_f(v.w));
        *reinterpret_cast<float4*>(&C[(size_t)m * ldc + n]) = g;
    } else if (EPI == 6) {               // (z2r + q) * gate -> token-major
        int bh = p >> 5, c = p & 31, b = bh >> 2, h = bh & 3;
        int tt = c * 64 + m;
        float4 q4 = *reinterpret_cast<const float4*>(&g_q[((size_t)p * 64 + m) * 128 + n]);
        float gt = g_gate[((size_t)(b * 2048 + tt)) * 4 + h];
        float4 r = make_float4((v.x + q4.x) * gt, (v.y + q4.y) * gt,
                               (v.z + q4.z) * gt, (v.w + q4.w) * gt);
        *reinterpret_cast<float4*>(&g_ret[((size_t)(b * 2048 + tt)) * 512 + h * 128 + n]) = r;
    }
}

// ---------------- gemm2: TM x 128 tile, BK=16, 2-stage (for TM=128 launches) ----
template<int TM, int TA, int TB, int EPI>
__global__ void __launch_bounds__(256, 2)
gemm2(const float* __restrict__ A, const float* __restrict__ B, float* __restrict__ C,
      int M, int N, int K, int lda, int ldb, int ldc,
      long sA, long sB, long sC)
{
    constexpr int MR = TM / 16;
    __shared__ __align__(16) float As[2][TM][20];     // row stride 80B (16B multiple)
    __shared__ __align__(16) float Bs[2][16][128];

    int p = blockIdx.z;
    A += (size_t)p * sA;
    B += (size_t)p * sB;
    C += (size_t)p * sC;

    int n0 = blockIdx.x * 128;
    int m0 = blockIdx.y * TM;
    int tid = threadIdx.x;
    int tx = tid & 15, ty = tid >> 4;

    auto stage = [&](int kt, int buf) {
        int k0 = kt * 16;
        if (TA == 0) {
            #pragma unroll
            for (int r = 0; r < TM/64; r++) {
                int e = tid + r * 256;
                int mm = e >> 2, kc = (e & 3) * 4;
                cpa16(s2u(&As[buf][mm][kc]), A + (size_t)(m0 + mm) * lda + (k0 + kc));
            }
        } else {
            #pragma unroll
            for (int r = 0; r < TM/16; r++) {
                int e = tid + r * 256;
                int mm = e % TM, kk = e / TM;
                cpa4(s2u(&As[buf][mm][kk]), A + (size_t)(k0 + kk) * lda + (m0 + mm));
            }
        }
        if (TB == 0) {
            #pragma unroll
            for (int r = 0; r < 2; r++) {
                int e = tid + r * 256;
                int kk = e >> 5, nc = (e & 31) * 4;
                cpa16(s2u(&Bs[buf][kk][nc]), B + (size_t)(k0 + kk) * ldb + (n0 + nc));
            }
        } else {
            #pragma unroll
            for (int r = 0; r < 8; r++) {
                int e = tid + r * 256;
                int kk = e & 15, nn = e >> 4;
                cpa4(s2u(&Bs[buf][kk][nn]), B + (size_t)(n0 + nn) * ldb + (k0 + kk));
            }
        }
    };

    unsigned long long acc[MR][4];
    #pragma unroll
    for (int i = 0; i < MR; i++)
        #pragma unroll
        for (int j = 0; j < 4; j++) acc[i][j] = 0ull;

    int ktiles = K / 16;
    stage(0, 0); CP_COMMIT();

    for (int t = 0; t < ktiles; t++) {
        int cur = t & 1;
        if (t + 1 < ktiles) {
            stage(t + 1, cur ^ 1); CP_COMMIT();
            asm volatile("cp.async.wait_group 1;" ::: "memory");
        } else {
            asm volatile("cp.async.wait_group 0;" ::: "memory");
        }
        __syncthreads();
        #pragma unroll
        for (int k = 0; k < 16; k++) {
            unsigned long long bv[4];
            {
                ulonglong2 q0 = *reinterpret_cast<const ulonglong2*>(&Bs[cur][k][tx * 8]);
                ulonglong2 q1 = *reinterpret_cast<const ulonglong2*>(&Bs[cur][k][tx * 8 + 4]);
                bv[0] = q0.x; bv[1] = q0.y; bv[2] = q1.x; bv[3] = q1.y;
            }
            #pragma unroll
            for (int i = 0; i < MR; i++) {
                unsigned a = __float_as_uint(As[cur][ty * MR + i][k]);
                unsigned long long a2;
                asm("mov.b64 %0, {%1, %1};" : "=l"(a2) : "r"(a));
                #pragma unroll
                for (int jp = 0; jp < 4; jp++)
                    asm("fma.rn.f32x2 %0, %1, %2, %0;"
                        : "+l"(acc[i][jp]) : "l"(a2), "l"(bv[jp]));
            }
        }
        __syncthreads();
    }

    #pragma unroll
    for (int i = 0; i < MR; i++) {
        int m = m0 + ty * MR + i;
        #pragma unroll
        for (int jq = 0; jq < 2; jq++) {
            int n = n0 + tx * 8 + jq * 4;
            float4 v;
            v.x = __uint_as_float((unsigned)(acc[i][2*jq]     & 0xffffffffull));
            v.y = __uint_as_float((unsigned)(acc[i][2*jq]    >> 32));
            v.z = __uint_as_float((unsigned)(acc[i][2*jq + 1] & 0xffffffffull));
            v.w = __uint_as_float((unsigned)(acc[i][2*jq + 1]>> 32));
            epi_store<EPI>(C, ldc, blockIdx.z, m, n, v);
        }
    }
}

// ---------------- gemm3: 64 x 128 tile, A k-major, 3-stage, 1 sync/tile ----
// A is [M,K] rowmajor (TA=0 only). TB=0: B [K,N]; TB=1: B [N,K] (op=B^T).
// Requires M % 64 == 0, N % 128 == 0, K % 16 == 0.
template<int TB, int EPI>
__global__ void __launch_bounds__(256, 3)
gemm3(const float* __restrict__ A, const float* __restrict__ B, float* __restrict__ C,
      int M, int N, int K, int lda, int ldb, int ldc,
      long sA, long sB, long sC)
{
    __shared__ __align__(16) float As[3][16][68];    // k-major, row 272B (17x16B)
    __shared__ __align__(16) float Bs[3][16][128];

    int p = blockIdx.z;
    A += (size_t)p * sA;
    B += (size_t)p * sB;
    C += (size_t)p * sC;

    int n0 = blockIdx.x * 128;
    int m0 = blockIdx.y * 64;
    int tid = threadIdx.x;
    int tx = tid & 15, ty = tid >> 4;

    auto stage = [&](int kt, int buf) {
        int k0 = kt * 16;
        // A: 64x16 -> k-major transpose, 4 elems/thread (global reads k-contiguous)
        #pragma unroll
        for (int r = 0; r < 4; r++) {
            int e = tid + r * 256;
            int kk = e & 15, mm = e >> 4;
            cpa4(s2u(&As[buf][kk][mm]), A + (size_t)(m0 + mm) * lda + (k0 + kk));
        }
        if (TB == 0) {
            #pragma unroll
            for (int r = 0; r < 2; r++) {
                int e = tid + r * 256;
                int kk = e >> 5, nc = (e & 31) * 4;
                cpa16(s2u(&Bs[buf][kk][nc]), B + (size_t)(k0 + kk) * ldb + (n0 + nc));
            }
        } else {
            #pragma unroll
            for (int r = 0; r < 8; r++) {
                int e = tid + r * 256;
                int kk = e & 15, nn = e >> 4;
                cpa4(s2u(&Bs[buf][kk][nn]), B + (size_t)(n0 + nn) * ldb + (k0 + kk));
            }
        }
    };

    unsigned long long acc[4][4];
    #pragma unroll
    for (int i = 0; i < 4; i++)
        #pragma unroll
        for (int j = 0; j < 4; j++) acc[i][j] = 0ull;

    int ktiles = K / 16;
    stage(0, 0); CP_COMMIT();
    stage(1, 1); CP_COMMIT();

    int cur = 0;
    for (int t = 0; t < ktiles; t++) {
        if (t + 1 < ktiles) asm volatile("cp.async.wait_group 1;" ::: "memory");
        else                asm volatile("cp.async.wait_group 0;" ::: "memory");
        __syncthreads();                 // publishes everyone's stage(t); orders vs compute(t-1)
        if (t + 2 < ktiles) {
            int nb = cur + 2; if (nb >= 3) nb -= 3;
            stage(t + 2, nb); CP_COMMIT();
        }
        #pragma unroll
        for (int k = 0; k < 16; k++) {
            unsigned long long bv[4];
            {
                ulonglong2 q0 = *reinterpret_cast<const ulonglong2*>(&Bs[cur][k][tx * 8]);
                ulonglong2 q1 = *reinterpret_cast<const ulonglong2*>(&Bs[cur][k][tx * 8 + 4]);
                bv[0] = q0.x; bv[1] = q0.y; bv[2] = q1.x; bv[3] = q1.y;
            }
            float4 a4 = *reinterpret_cast<const float4*>(&As[cur][k][ty * 4]);
            #pragma unroll
            for (int i = 0; i < 4; i++) {
                float aval = (i == 0) ? a4.x : (i == 1) ? a4.y : (i == 2) ? a4.z : a4.w;
                unsigned a = __float_as_uint(aval);
                unsigned long long a2;
                asm("mov.b64 %0, {%1, %1};" : "=l"(a2) : "r"(a));
                #pragma unroll
                for (int jp = 0; jp < 4; jp++)
                    asm("fma.rn.f32x2 %0, %1, %2, %0;"
                        : "+l"(acc[i][jp]) : "l"(a2), "l"(bv[jp]));
            }
        }
        cur = (cur + 1 == 3) ? 0 : cur + 1;
    }

    #pragma unroll
    for (int i = 0; i < 4; i++) {
        int m = m0 + ty * 4 + i;
        #pragma unroll
        for (int jq = 0; jq < 2; jq++) {
            int n = n0 + tx * 8 + jq * 4;
            float4 v;
            v.x = __uint_as_float((unsigned)(acc[i][2*jq]     & 0xffffffffull));
            v.y = __uint_as_float((unsigned)(acc[i][2*jq]    >> 32));
            v.z = __uint_as_float((unsigned)(acc[i][2*jq + 1] & 0xffffffffull));
            v.w = __uint_as_float((unsigned)(acc[i][2*jq + 1]>> 32));
            epi_store<EPI>(C, ldc, blockIdx.z, m, n, v);
        }
    }
}

// ---------------- elementwise / reduction kernels ----------------

__global__ void norms_kernel(const float* __restrict__ seq,
                             const float* __restrict__ gs,
                             const float* __restrict__ gr)
{
    int row = blockIdx.x;
    int tid = threadIdx.x;                       // 256
    const float* x = seq + (size_t)row * 512;
    float a = x[tid], b = x[tid + 256];
    float ss = blk_sum<256>(a * a + b * b);
    float r = rsqrtf(ss * (1.0f / 512.0f) + 1e-6f);
    g_xs[(size_t)row * 512 + tid]       = a * r * gs[tid];
    g_xs[(size_t)row * 512 + tid + 256] = b * r * gs[tid + 256];
    g_xr[(size_t)row * 512 + tid]       = a * r * gr[tid];
    g_xr[(size_t)row * 512 + tid + 256] = b * r * gr[tid + 256];
}

__global__ void pooled_gates_kernel(const float* __restrict__ Wm,
                                    const float* __restrict__ Wd,
                                    const float* __restrict__ bd)
{
    __shared__ float sm[512];
    int blk = blockIdx.x;                        // b*32 + c
    int b = blk >> 5, c = blk & 31;
    int tid = threadIdx.x;                       // 256
    const float* base = g_xs + ((size_t)(b * 2048 + c * 64)) * 512;
    float s0 = 0.0f, s1 = 0.0f;
    for (int i = 0; i < 64; i++) {
        s0 += base[(size_t)i * 512 + tid];
        s1 += base[(size_t)i * 512 + tid + 256];
    }
    sm[tid]       = s0 * (1.0f / 64.0f);
    sm[tid + 256] = s1 * (1.0f / 64.0f);
    __syncthreads();
    int w = tid >> 5, lane = tid & 31;
    if (w < 4) {
        float pm = 0.0f, pd = 0.0f;
        for (int d = lane; d < 512; d += 32) {
            float pv = sm[d];
            pm += pv * Wm[d * 4 + w];
            pd += pv * Wd[d * 4 + w];
        }
        #pragma unroll
        for (int o = 16; o > 0; o >>= 1) {
            pm += __shfl_xor_sync(0xffffffffu, pm, o);
            pd += __shfl_xor_sync(0xffffffffu, pd, o);
        }
        if (lane == 0) {
            g_beta [c * 8 + b * 4 + w] = sigm(pm);
            g_alpha[c * 8 + b * 4 + w] = 1.0f - sigm(pd + bd[w]);
        }
    }
}

__global__ void lrgate_kernel(const float* __restrict__ Wa,
                              const float* __restrict__ ba,
                              const float* __restrict__ Wg)
{
    int r = blockIdx.x;
    int tid = threadIdx.x;                       // 128
    int w = tid >> 5, lane = tid & 31;
    float pa = 0.0f, pg = 0.0f;
    for (int d = lane; d < 512; d += 32) {
        pa += g_xs[(size_t)r * 512 + d] * Wa[d * 4 + w];
        pg += g_xr[(size_t)r * 512 + d] * Wg[d * 4 + w];
    }
    #pragma unroll
    for (int o = 16; o > 0; o >>= 1) {
        pa += __shfl_xor_sync(0xffffffffu, pa, o);
        pg += __shfl_xor_sync(0xffffffffu, pg, o);
    }
    if (lane == 0) {
        int b = r >> 11, t = r & 2047, c = t >> 6, i = t & 63;
        g_lr[((size_t)((b * 4 + w) * 32 + c)) * 64 + i] = sigm(pa + ba[w]);
        g_gate[(size_t)r * 4 + w] = sigm(pg);
    }
}

__global__ void normk_kernel(const float* __restrict__ memg)
{
    int row = blockIdx.x;                        // 16384
    int d = threadIdx.x;                         // 128
    float x = g_k[(size_t)row * 128 + d];
    float ss = blk_sum<128>(x * x);
    float r = rsqrtf(ss * (1.0f / 128.0f) + 1e-6f);
    float u = x * r;
    g_u[(size_t)row * 128 + d] = u;
    g_h[(size_t)row * 128 + d] = u * memg[d];
}

__global__ void dg_kernel()
{
    int p = blockIdx.x;
    int d = threadIdx.x;
    float s = 0.0f;
    size_t base = (size_t)p * 64 * 128 + d;
    for (int i = 0; i < 64; i++)
        s += g_dh[base + (size_t)i * 128] * g_u[base + (size_t)i * 128];
    g_gg[(size_t)p * 128 + d] = s;
}

__global__ void scan_kernel(const float* __restrict__ memg,
                            const float* __restrict__ w1,
                            const float* __restrict__ w2)
{
    __shared__ float sb[NCn], sa[NCn];
    int tid = threadIdx.x;
    int bh = blockIdx.y;
    if (tid < NCn) {
        sb[tid] = g_beta [tid * BHn + bh];
        sa[tid] = g_alpha[tid * BHn + bh];
    }
    __syncthreads();
    const int E = DHn + DHn * DHIDn + DHIDn * DHn;   // 131200
    int e = blockIdx.x * blockDim.x + tid;
    if (e >= E) return;

    float w, m = 0.0f;
    const float* grad;
    float* wprev;
    size_t str;
    if (e < DHn) {
        w = memg[e];
        grad  = g_gg + (size_t)bh * 32 * 128 + e;
        wprev = g_gp + (size_t)bh * 32 * 128 + e;
        str = 128;
    } else if (e < DHn + DHn * DHIDn) {
        size_t o = e - DHn;
        w = w1[o];
        grad  = g_gw1 + (size_t)bh * 32 * 65536 + o;
        wprev = g_w1p + (size_t)bh * 32 * 65536 + o;
        str = 65536;
    } else {
        size_t o = e - DHn - DHn * DHIDn;
        w = w2[o];
        grad  = g_gw2 + (size_t)bh * 32 * 65536 + o;
        wprev = g_w2p + (size_t)bh * 32 * 65536 + o;
        str = 65536;
    }
    #pragma unroll 4
    for (int c = 0; c < NCn; c++) {
        wprev[(size_t)c * str] = w;                  // w_{c-1} seen by chunk c
        m = sb[c] * m - grad[(size_t)c * str];       // surprise = -grad
        w = sa[c] * w + m;
    }
}

__global__ void hq_kernel()
{
    int row = blockIdx.x;                        // 16384
    int d = threadIdx.x;                         // 128
    int p = row >> 6;
    float x = g_q[(size_t)row * 128 + d];
    float ss = blk_sum<128>(x * x);
    float r = rsqrtf(ss * (1.0f / 128.0f) + 1e-6f);
    g_hq[(size_t)row * 128 + d] = x * r * g_gp[(size_t)p * 128 + d];
}

// ---------------- launch ----------------
extern "C" void kernel_launch(void* const* d_in, const int* in_sizes, int n_in,
                              void* d_out, int out_size)
{
    (void)in_sizes; (void)n_in; (void)out_size;
    const float* seq  = (const float*)d_in[0];
    const float* gsn  = (const float*)d_in[1];
    const float* grn  = (const float*)d_in[2];
    const float* Wq   = (const float*)d_in[3];
    const float* Wk   = (const float*)d_in[4];
    const float* Wv   = (const float*)d_in[5];
    const float* Wa   = (const float*)d_in[6];
    const float* ba   = (const float*)d_in[7];
    const float* Wm   = (const float*)d_in[8];
    const float* Wd   = (const float*)d_in[9];
    const float* bd   = (const float*)d_in[10];
    const float* Wg   = (const float*)d_in[11];
    const float* Wc   = (const float*)d_in[12];
    const float* memg = (const float*)d_in[13];
    const float* w1   = (const float*)d_in[14];
    const float* w2   = (const float*)d_in[15];
    float* out = (float*)d_out;

    float* pz1 = nullptr; float* pk = nullptr; float* pv = nullptr; float* pq = nullptr;
    float* pdp = nullptr; float* pdz = nullptr; float* pdh = nullptr;
    float* pgw1 = nullptr; float* pgw2 = nullptr; float* ph = nullptr; float* phq = nullptr;
    float* pa1 = nullptr; float* pw1p = nullptr; float* pw2p = nullptr; float* pret = nullptr;
    float* pxs = nullptr; float* pxr = nullptr;
    cudaGetSymbolAddress((void**)&pz1,  g_z1);
    cudaGetSymbolAddress((void**)&pk,   g_k);
    cudaGetSymbolAddress((void**)&pv,   g_v);
    cudaGetSymbolAddress((void**)&pq,   g_q);
    cudaGetSymbolAddress((void**)&pdp,  g_dpred);
    cudaGetSymbolAddress((void**)&pdz,  g_dz1);
    cudaGetSymbolAddress((void**)&pdh,  g_dh);
    cudaGetSymbolAddress((void**)&pgw1, g_gw1);
    cudaGetSymbolAddress((void**)&pgw2, g_gw2);
    cudaGetSymbolAddress((void**)&ph,   g_h);
    cudaGetSymbolAddress((void**)&phq,  g_hq);
    cudaGetSymbolAddress((void**)&pa1,  g_a1);
    cudaGetSymbolAddress((void**)&pw1p, g_w1p);
    cudaGetSymbolAddress((void**)&pw2p, g_w2p);
    cudaGetSymbolAddress((void**)&pret, g_ret);
    cudaGetSymbolAddress((void**)&pxs,  g_xs);
    cudaGetSymbolAddress((void**)&pxr,  g_xr);

    // 1. token norms
    norms_kernel<<<ROWS, 256>>>(seq, gsn, grn);

    // 2. pooled stats -> beta/alpha
    pooled_gates_kernel<<<Bn * NCn, 256>>>(Wm, Wd, bd);

    // 3. projections (remap to chunk-major)
    gemm3<0,1><<<dim3(4, 64, 1), 256>>>(pxs, Wk, pk, ROWS, 512, 512, 512, 512, 0, 0, 0, 0);
    gemm3<0,1><<<dim3(4, 64, 1), 256>>>(pxs, Wv, pv, ROWS, 512, 512, 512, 512, 0, 0, 0, 0);
    gemm3<0,1><<<dim3(4, 64, 1), 256>>>(pxr, Wq, pq, ROWS, 512, 512, 512, 512, 0, 0, 0, 0);

    // 4. lr + gate
    lrgate_kernel<<<ROWS, 128>>>(Wa, ba, Wg);

    // 5. k-row RMS -> u, h
    normk_kernel<<<KROWS, 128>>>(memg);

    // 6. z1 = h @ w1 (+ gelu -> a1)
    gemm2<128,0,0,2><<<dim3(4, 128, 1), 256>>>(ph, w1, pz1, KROWS, 512, 128, 128, 512, 512, 0, 0, 0);

    // 7. z2 = a1 @ w2 -> dpred (fused)
    gemm3<0,3><<<dim3(1, 256, 1), 256>>>(pa1, w2, pdp, KROWS, 128, 512, 512, 128, 128, 0, 0, 0);

    // 8. dW2 = a1^T @ dpred (batched over 256 chunks)
    gemm2<128,1,0,0><<<dim3(1, 4, Pn), 256>>>(pa1, pdp, pgw2, 512, 128, 64, 512, 128, 128,
                                              64L * 512, 64L * 128, 512L * 128);

    // 9. dz1 = (dpred @ w2^T) * gelu'(z1)
    gemm2<128,0,1,4><<<dim3(4, 128, 1), 256>>>(pdp, w2, pdz, KROWS, 512, 128, 128, 128, 512, 0, 0, 0);

    // 10. dW1 = h^T @ dz1 (batched)
    gemm2<128,1,0,0><<<dim3(4, 1, Pn), 256>>>(ph, pdz, pgw1, 128, 512, 64, 128, 512, 512,
                                              64L * 128, 64L * 512, 128L * 512);

    // 11. dh = dz1 @ w1^T
    gemm3<1,0><<<dim3(1, 256, 1), 256>>>(pdz, w1, pdh, KROWS, 128, 512, 512, 512, 128, 0, 0, 0);

    // 12. dg reduction
    dg_kernel<<<Pn, 128>>>();

    // 13. momentum + decay scan, writes per-chunk w_prev
    {
        const int E = DHn + DHn * DHIDn + DHIDn * DHn;
        scan_kernel<<<dim3((E + 255) / 256, BHn), 256>>>(memg, w1, w2);
    }

    // 14. q-row RMS scaled by g_prev
    hq_kernel<<<KROWS, 128>>>();

    // 15. z1r = hq @ w1_prev (batched, gelu -> a1 reuse). M=64 per chunk.
    gemm3<0,5><<<dim3(4, 1, Pn), 256>>>(phq, pw1p, pa1, 64, 512, 128, 128, 512, 512,
                                        64L * 128, 128L * 512, 64L * 512);

    // 16. z2r = a1r @ w2_prev -> (.. + q) * gate, token-major
    gemm3<0,6><<<dim3(1, 1, Pn), 256>>>(pa1, pw2p, pret, 64, 128, 512, 512, 128, 128,
                                        64L * 512, 512L * 128, 0);

    // 17. combine: out = ret @ Wc
    gemm3<0,0><<<dim3(4, 64, 1), 256>>>(pret, Wc, out, ROWS, 512, 512, 512, 512, 512, 0, 0, 0);
}

// round 12
// speedup vs baseline: 1.2500x; 1.2500x over previous
#include <cuda_runtime.h>
#include <cuda_bf16.h>
#include <math.h>

// ---------------- problem constants ----------------
#define Bn    2
#define Nn    2048
#define DIMn  512
#define Hn    4
#define DHn   128
#define CH    64
#define NCn   32
#define BHn   8
#define Pn    256            // BH * NC
#define DHIDn 512
#define ROWS  (Bn*Nn)        // 4096 tokens
#define KROWS (Pn*CH)        // 16384 chunk-major rows

// ---------------- static scratch (no cudaMalloc allowed) ----------------
__device__ float g_xs[ROWS*DIMn];
__device__ float g_xr[ROWS*DIMn];
__device__ float g_q [KROWS*DHn];
__device__ float g_k [KROWS*DHn];
__device__ float g_v [KROWS*DHn];
__device__ float g_u [KROWS*DHn];
__device__ float g_h [KROWS*DHn];
__device__ float g_hq[KROWS*DHn];
__device__ float g_lr[KROWS];
__device__ float g_gate[ROWS*Hn];
__device__ float g_beta [NCn*BHn];
__device__ float g_alpha[NCn*BHn];
__device__ float g_z1 [KROWS*DHIDn];
__device__ float g_a1 [KROWS*DHIDn];
__device__ float g_dz1[KROWS*DHIDn];
__device__ float g_dpred[KROWS*DHn];
__device__ float g_dh  [KROWS*DHn];
__device__ float g_gg [Pn*DHn];
__device__ float g_gw1[Pn*DHn*DHIDn];
__device__ float g_gw2[Pn*DHIDn*DHn];
__device__ float g_gp [Pn*DHn];
__device__ float g_w1p[(size_t)Pn*DHn*DHIDn];
__device__ float g_w2p[(size_t)Pn*DHIDn*DHn];
__device__ float g_ret[ROWS*DIMn];

// ---------------- small helpers ----------------
__device__ __forceinline__ float sigm(float x) { return 1.0f / (1.0f + expf(-x)); }
__device__ __forceinline__ float gelu_f(float x) {
    return 0.5f * x * (1.0f + erff(x * 0.70710678118654752f));
}
__device__ __forceinline__ float gelu_grad_f(float x) {
    float c = 0.5f * (1.0f + erff(x * 0.70710678118654752f));
    return c + x * 0.3989422804014327f * expf(-0.5f * x * x);
}

__device__ __forceinline__ unsigned s2u(const void* p) {
    return (unsigned)__cvta_generic_to_shared(p);
}
__device__ __forceinline__ void cpa16(unsigned d, const void* s) {
    asm volatile("cp.async.cg.shared.global [%0], [%1], 16;" :: "r"(d), "l"(s));
}
__device__ __forceinline__ void cpa4(unsigned d, const void* s) {
    asm volatile("cp.async.ca.shared.global [%0], [%1], 4;" :: "r"(d), "l"(s));
}
#define CP_COMMIT() asm volatile("cp.async.commit_group;" ::: "memory")

template<int NT>
__device__ __forceinline__ float blk_sum(float v) {
    __shared__ float sbuf[NT/32];
    int tid = threadIdx.x;
    #pragma unroll
    for (int o = 16; o > 0; o >>= 1) v += __shfl_xor_sync(0xffffffffu, v, o);
    if ((tid & 31) == 0) sbuf[tid >> 5] = v;
    __syncthreads();
    float s = (tid < NT/32) ? sbuf[tid] : 0.0f;
    if (tid < 32) {
        #pragma unroll
        for (int o = NT/64; o > 0; o >>= 1) s += __shfl_xor_sync(0xffffffffu, s, o);
        if (tid == 0) sbuf[0] = s;
    }
    __syncthreads();
    s = sbuf[0];
    __syncthreads();
    return s;
}

// epilogue: one float4 quad
template<int EPI>
__device__ __forceinline__ void epi_store(float* __restrict__ C, int ldc, int p,
                                          int m, int n, float4 v)
{
    if (EPI == 0) {                      // plain
        *reinterpret_cast<float4*>(&C[(size_t)m * ldc + n]) = v;
    } else if (EPI == 1) {               // qkv remap token->chunk (quad stays in-head)
        int b = m >> 11, tt = m & 2047, c = tt >> 6, ii = tt & 63;
        int h = n >> 7, d = n & 127;
        size_t o = ((size_t)((b * 4 + h) * 32 + c)) * (64 * 128) + ii * 128 + d;
        *reinterpret_cast<float4*>(&C[o]) = v;
    } else if (EPI == 2) {               // z1 + gelu -> a1
        size_t o = (size_t)m * 512 + n;
        *reinterpret_cast<float4*>(&C[o]) = v;
        float4 g = make_float4(gelu_f(v.x), gelu_f(v.y), gelu_f(v.z), gelu_f(v.w));
        *reinterpret_cast<float4*>(&g_a1[o]) = g;
    } else if (EPI == 3) {               // dpred = 2*lr/DH * (z2 + k - v)
        size_t o = (size_t)m * 128 + n;
        float4 kk4 = *reinterpret_cast<const float4*>(&g_k[o]);
        float4 vv4 = *reinterpret_cast<const float4*>(&g_v[o]);
        float s = g_lr[m] * (2.0f / 128.0f);
        float4 r = make_float4((v.x + kk4.x - vv4.x) * s, (v.y + kk4.y - vv4.y) * s,
                               (v.z + kk4.z - vv4.z) * s, (v.w + kk4.w - vv4.w) * s);
        *reinterpret_cast<float4*>(&C[o]) = r;
    } else if (EPI == 4) {               // dz1 = da1 * gelu'(z1)
        size_t o = (size_t)m * 512 + n;
        float4 z4 = *reinterpret_cast<const float4*>(&g_z1[o]);
        float4 r = make_float4(v.x * gelu_grad_f(z4.x), v.y * gelu_grad_f(z4.y),
                               v.z * gelu_grad_f(z4.z), v.w * gelu_grad_f(z4.w));
        *reinterpret_cast<float4*>(&C[o]) = r;
    } else if (EPI == 5) {               // a1r = gelu(z1r)
        float4 g = make_float4(gelu_f(v.x), gelu_f(v.y), gelu_f(v.z), gelu_f(v.w));
        *reinterpret_cast<float4*>(&C[(size_t)m * ldc + n]) = g;
    } else if (EPI == 6) {               // (z2r + q) * gate -> token-major
        int bh = p >> 5, c = p & 31, b = bh >> 2, h = bh & 3;
        int tt = c * 64 + m;
        float4 q4 = *reinterpret_cast<const float4*>(&g_q[((size_t)p * 64 + m) * 128 + n]);
        float gt = g_gate[((size_t)(b * 2048 + tt)) * 4 + h];
        float4 r = make_float4((v.x + q4.x) * gt, (v.y + q4.y) * gt,
                               (v.z + q4.z) * gt, (v.w + q4.w) * gt);
        *reinterpret_cast<float4*>(&g_ret[((size_t)(b * 2048 + tt)) * 512 + h * 128 + n]) = r;
    }
}

// ---------------- gemm4: 64x128 tile, 128 threads, 8x8 microtile, 3-stage ----
// TA=0: A [M,K] rowmajor. TA=1: A [K,M] rowmajor (op=A^T).
// TB=0: B [K,N] rowmajor. TB=1: B [N,K] rowmajor (op=B^T).
// Requires M % 64 == 0, N % 128 == 0, K % 16 == 0.
template<int TA, int TB, int EPI>
__global__ void __launch_bounds__(128, 4)
gemm4(const float* __restrict__ A, const float* __restrict__ B, float* __restrict__ C,
      int M, int N, int K, int lda, int ldb, int ldc,
      long sA, long sB, long sC)
{
    __shared__ __align__(16) float As[3][16][72];    // k-major, row 288B (18x16B)
    __shared__ __align__(16) float Bs[3][16][128];

    int p = blockIdx.z;
    A += (size_t)p * sA;
    B += (size_t)p * sB;
    C += (size_t)p * sC;

    int n0 = blockIdx.x * 128;
    int m0 = blockIdx.y * 64;
    int tid = threadIdx.x;
    int tx = tid & 15, ty = tid >> 4;               // tx: 8 n-floats, ty: 8 m-floats

    auto stage = [&](int kt, int buf) {
        int k0 = kt * 16;
        if (TA == 0) {
            // A [M,K]: transpose 64x16 -> k-major, 8 scalars/thread
            #pragma unroll
            for (int r = 0; r < 8; r++) {
                int e = tid + r * 128;
                int kk = e & 15, mm = e >> 4;
                cpa4(s2u(&As[buf][kk][mm]), A + (size_t)(m0 + mm) * lda + (k0 + kk));
            }
        } else {
            // A [K,M]: rows are m-contiguous, 2 cpa16/thread
            #pragma unroll
            for (int r = 0; r < 2; r++) {
                int e = tid + r * 128;
                int kk = e >> 4, mc = (e & 15) * 4;
                cpa16(s2u(&As[buf][kk][mc]), A + (size_t)(k0 + kk) * lda + (m0 + mc));
            }
        }
        if (TB == 0) {
            // B [K,N]: 4 cpa16/thread
            #pragma unroll
            for (int r = 0; r < 4; r++) {
                int e = tid + r * 128;
                int kk = e >> 5, nc = (e & 31) * 4;
                cpa16(s2u(&Bs[buf][kk][nc]), B + (size_t)(k0 + kk) * ldb + (n0 + nc));
            }
        } else {
            // B [N,K]: transpose, 16 scalars/thread
            #pragma unroll
            for (int r = 0; r < 16; r++) {
                int e = tid + r * 128;
                int kk = e & 15, nn = e >> 4;
                cpa4(s2u(&Bs[buf][kk][nn]), B + (size_t)(n0 + nn) * ldb + (k0 + kk));
            }
        }
    };

    unsigned long long acc[8][4];
    #pragma unroll
    for (int i = 0; i < 8; i++)
        #pragma unroll
        for (int j = 0; j < 4; j++) acc[i][j] = 0ull;

    int ktiles = K / 16;
    stage(0, 0); CP_COMMIT();
    stage(1, 1); CP_COMMIT();

    int cur = 0;
    for (int t = 0; t < ktiles; t++) {
        if (t + 1 < ktiles) asm volatile("cp.async.wait_group 1;" ::: "memory");
        else                asm volatile("cp.async.wait_group 0;" ::: "memory");
        __syncthreads();                 // publishes everyone's stage(t); orders vs compute(t-1)
        if (t + 2 < ktiles) {
            int nb = cur + 2; if (nb >= 3) nb -= 3;
            stage(t + 2, nb); CP_COMMIT();
        }
        #pragma unroll
        for (int k = 0; k < 16; k++) {
            unsigned long long bv[4];
            {
                ulonglong2 q0 = *reinterpret_cast<const ulonglong2*>(&Bs[cur][k][tx * 8]);
                ulonglong2 q1 = *reinterpret_cast<const ulonglong2*>(&Bs[cur][k][tx * 8 + 4]);
                bv[0] = q0.x; bv[1] = q0.y; bv[2] = q1.x; bv[3] = q1.y;
            }
            float4 a0 = *reinterpret_cast<const float4*>(&As[cur][k][ty * 8]);
            float4 a1 = *reinterpret_cast<const float4*>(&As[cur][k][ty * 8 + 4]);
            float av[8] = {a0.x, a0.y, a0.z, a0.w, a1.x, a1.y, a1.z, a1.w};
            #pragma unroll
            for (int i = 0; i < 8; i++) {
                unsigned a = __float_as_uint(av[i]);
                unsigned long long a2;
                asm("mov.b64 %0, {%1, %1};" : "=l"(a2) : "r"(a));
                #pragma unroll
                for (int jp = 0; jp < 4; jp++)
                    asm("fma.rn.f32x2 %0, %1, %2, %0;"
                        : "+l"(acc[i][jp]) : "l"(a2), "l"(bv[jp]));
            }
        }
        cur = (cur + 1 == 3) ? 0 : cur + 1;
    }

    #pragma unroll
    for (int i = 0; i < 8; i++) {
        int m = m0 + ty * 8 + i;
        #pragma unroll
        for (int jq = 0; jq < 2; jq++) {
            int n = n0 + tx * 8 + jq * 4;
            float4 v;
            v.x = __uint_as_float((unsigned)(acc[i][2*jq]     & 0xffffffffull));
            v.y = __uint_as_float((unsigned)(acc[i][2*jq]    >> 32));
            v.z = __uint_as_float((unsigned)(acc[i][2*jq + 1] & 0xffffffffull));
            v.w = __uint_as_float((unsigned)(acc[i][2*jq + 1]>> 32));
            epi_store<EPI>(C, ldc, blockIdx.z, m, n, v);
        }
    }
}

// ---------------- elementwise / reduction kernels ----------------

__global__ void norms_kernel(const float* __restrict__ seq,
                             const float* __restrict__ gs,
                             const float* __restrict__ gr)
{
    int row = blockIdx.x;
    int tid = threadIdx.x;                       // 256
    const float* x = seq + (size_t)row * 512;
    float a = x[tid], b = x[tid + 256];
    float ss = blk_sum<256>(a * a + b * b);
    float r = rsqrtf(ss * (1.0f / 512.0f) + 1e-6f);
    g_xs[(size_t)row * 512 + tid]       = a * r * gs[tid];
    g_xs[(size_t)row * 512 + tid + 256] = b * r * gs[tid + 256];
    g_xr[(size_t)row * 512 + tid]       = a * r * gr[tid];
    g_xr[(size_t)row * 512 + tid + 256] = b * r * gr[tid + 256];
}

__global__ void pooled_gates_kernel(const float* __restrict__ Wm,
                                    const float* __restrict__ Wd,
                                    const float* __restrict__ bd)
{
    __shared__ float sm[512];
    int blk = blockIdx.x;                        // b*32 + c
    int b = blk >> 5, c = blk & 31;
    int tid = threadIdx.x;                       // 256
    const float* base = g_xs + ((size_t)(b * 2048 + c * 64)) * 512;
    float s0 = 0.0f, s1 = 0.0f;
    for (int i = 0; i < 64; i++) {
        s0 += base[(size_t)i * 512 + tid];
        s1 += base[(size_t)i * 512 + tid + 256];
    }
    sm[tid]       = s0 * (1.0f / 64.0f);
    sm[tid + 256] = s1 * (1.0f / 64.0f);
    __syncthreads();
    int w = tid >> 5, lane = tid & 31;
    if (w < 4) {
        float pm = 0.0f, pd = 0.0f;
        for (int d = lane; d < 512; d += 32) {
            float pv = sm[d];
            pm += pv * Wm[d * 4 + w];
            pd += pv * Wd[d * 4 + w];
        }
        #pragma unroll
        for (int o = 16; o > 0; o >>= 1) {
            pm += __shfl_xor_sync(0xffffffffu, pm, o);
            pd += __shfl_xor_sync(0xffffffffu, pd, o);
        }
        if (lane == 0) {
            g_beta [c * 8 + b * 4 + w] = sigm(pm);
            g_alpha[c * 8 + b * 4 + w] = 1.0f - sigm(pd + bd[w]);
        }
    }
}

__global__ void lrgate_kernel(const float* __restrict__ Wa,
                              const float* __restrict__ ba,
                              const float* __restrict__ Wg)
{
    int r = blockIdx.x;
    int tid = threadIdx.x;                       // 128
    int w = tid >> 5, lane = tid & 31;
    float pa = 0.0f, pg = 0.0f;
    for (int d = lane; d < 512; d += 32) {
        pa += g_xs[(size_t)r * 512 + d] * Wa[d * 4 + w];
        pg += g_xr[(size_t)r * 512 + d] * Wg[d * 4 + w];
    }
    #pragma unroll
    for (int o = 16; o > 0; o >>= 1) {
        pa += __shfl_xor_sync(0xffffffffu, pa, o);
        pg += __shfl_xor_sync(0xffffffffu, pg, o);
    }
    if (lane == 0) {
        int b = r >> 11, t = r & 2047, c = t >> 6, i = t & 63;
        g_lr[((size_t)((b * 4 + w) * 32 + c)) * 64 + i] = sigm(pa + ba[w]);
        g_gate[(size_t)r * 4 + w] = sigm(pg);
    }
}

__global__ void normk_kernel(const float* __restrict__ memg)
{
    int row = blockIdx.x;                        // 16384
    int d = threadIdx.x;                         // 128
    float x = g_k[(size_t)row * 128 + d];
    float ss = blk_sum<128>(x * x);
    float r = rsqrtf(ss * (1.0f / 128.0f) + 1e-6f);
    float u = x * r;
    g_u[(size_t)row * 128 + d] = u;
    g_h[(size_t)row * 128 + d] = u * memg[d];
}

__global__ void dg_kernel()
{
    int p = blockIdx.x;
    int d = threadIdx.x;
    float s = 0.0f;
    size_t base = (size_t)p * 64 * 128 + d;
    for (int i = 0; i < 64; i++)
        s += g_dh[base + (size_t)i * 128] * g_u[base + (size_t)i * 128];
    g_gg[(size_t)p * 128 + d] = s;
}

__global__ void scan_kernel(const float* __restrict__ memg,
                            const float* __restrict__ w1,
                            const float* __restrict__ w2)
{
    __shared__ float sb[NCn], sa[NCn];
    int tid = threadIdx.x;
    int bh = blockIdx.y;
    if (tid < NCn) {
        sb[tid] = g_beta [tid * BHn + bh];
        sa[tid] = g_alpha[tid * BHn + bh];
    }
    __syncthreads();
    const int E = DHn + DHn * DHIDn + DHIDn * DHn;   // 131200
    int e = blockIdx.x * blockDim.x + tid;
    if (e >= E) return;

    float w, m = 0.0f;
    const float* grad;
    float* wprev;
    size_t str;
    if (e < DHn) {
        w = memg[e];
        grad  = g_gg + (size_t)bh * 32 * 128 + e;
        wprev = g_gp + (size_t)bh * 32 * 128 + e;
        str = 128;
    } else if (e < DHn + DHn * DHIDn) {
        size_t o = e - DHn;
        w = w1[o];
        grad  = g_gw1 + (size_t)bh * 32 * 65536 + o;
        wprev = g_w1p + (size_t)bh * 32 * 65536 + o;
        str = 65536;
    } else {
        size_t o = e - DHn - DHn * DHIDn;
        w = w2[o];
        grad  = g_gw2 + (size_t)bh * 32 * 65536 + o;
        wprev = g_w2p + (size_t)bh * 32 * 65536 + o;
        str = 65536;
    }
    #pragma unroll 4
    for (int c = 0; c < NCn; c++) {
        wprev[(size_t)c * str] = w;                  // w_{c-1} seen by chunk c
        m = sb[c] * m - grad[(size_t)c * str];       // surprise = -grad
        w = sa[c] * w + m;
    }
}

__global__ void hq_kernel()
{
    int row = blockIdx.x;                        // 16384
    int d = threadIdx.x;                         // 128
    int p = row >> 6;
    float x = g_q[(size_t)row * 128 + d];
    float ss = blk_sum<128>(x * x);
    float r = rsqrtf(ss * (1.0f / 128.0f) + 1e-6f);
    g_hq[(size_t)row * 128 + d] = x * r * g_gp[(size_t)p * 128 + d];
}

// ---------------- launch ----------------
extern "C" void kernel_launch(void* const* d_in, const int* in_sizes, int n_in,
                              void* d_out, int out_size)
{
    (void)in_sizes; (void)n_in; (void)out_size;
    const float* seq  = (const float*)d_in[0];
    const float* gsn  = (const float*)d_in[1];
    const float* grn  = (const float*)d_in[2];
    const float* Wq   = (const float*)d_in[3];
    const float* Wk   = (const float*)d_in[4];
    const float* Wv   = (const float*)d_in[5];
    const float* Wa   = (const float*)d_in[6];
    const float* ba   = (const float*)d_in[7];
    const float* Wm   = (const float*)d_in[8];
    const float* Wd   = (const float*)d_in[9];
    const float* bd   = (const float*)d_in[10];
    const float* Wg   = (const float*)d_in[11];
    const float* Wc   = (const float*)d_in[12];
    const float* memg = (const float*)d_in[13];
    const float* w1   = (const float*)d_in[14];
    const float* w2   = (const float*)d_in[15];
    float* out = (float*)d_out;

    float* pz1 = nullptr; float* pk = nullptr; float* pv = nullptr; float* pq = nullptr;
    float* pdp = nullptr; float* pdz = nullptr; float* pdh = nullptr;
    float* pgw1 = nullptr; float* pgw2 = nullptr; float* ph = nullptr; float* phq = nullptr;
    float* pa1 = nullptr; float* pw1p = nullptr; float* pw2p = nullptr; float* pret = nullptr;
    float* pxs = nullptr; float* pxr = nullptr;
    cudaGetSymbolAddress((void**)&pz1,  g_z1);
    cudaGetSymbolAddress((void**)&pk,   g_k);
    cudaGetSymbolAddress((void**)&pv,   g_v);
    cudaGetSymbolAddress((void**)&pq,   g_q);
    cudaGetSymbolAddress((void**)&pdp,  g_dpred);
    cudaGetSymbolAddress((void**)&pdz,  g_dz1);
    cudaGetSymbolAddress((void**)&pdh,  g_dh);
    cudaGetSymbolAddress((void**)&pgw1, g_gw1);
    cudaGetSymbolAddress((void**)&pgw2, g_gw2);
    cudaGetSymbolAddress((void**)&ph,   g_h);
    cudaGetSymbolAddress((void**)&phq,  g_hq);
    cudaGetSymbolAddress((void**)&pa1,  g_a1);
    cudaGetSymbolAddress((void**)&pw1p, g_w1p);
    cudaGetSymbolAddress((void**)&pw2p, g_w2p);
    cudaGetSymbolAddress((void**)&pret, g_ret);
    cudaGetSymbolAddress((void**)&pxs,  g_xs);
    cudaGetSymbolAddress((void**)&pxr,  g_xr);

    // 1. token norms
    norms_kernel<<<ROWS, 256>>>(seq, gsn, grn);

    // 2. pooled stats -> beta/alpha
    pooled_gates_kernel<<<Bn * NCn, 256>>>(Wm, Wd, bd);

    // 3. projections (remap to chunk-major)
    gemm4<0,0,1><<<dim3(4, 64, 1), 128>>>(pxs, Wk, pk, ROWS, 512, 512, 512, 512, 0, 0, 0, 0);
    gemm4<0,0,1><<<dim3(4, 64, 1), 128>>>(pxs, Wv, pv, ROWS, 512, 512, 512, 512, 0, 0, 0, 0);
    gemm4<0,0,1><<<dim3(4, 64, 1), 128>>>(pxr, Wq, pq, ROWS, 512, 512, 512, 512, 0, 0, 0, 0);

    // 4. lr + gate
    lrgate_kernel<<<ROWS, 128>>>(Wa, ba, Wg);

    // 5. k-row RMS -> u, h
    normk_kernel<<<KROWS, 128>>>(memg);

    // 6. z1 = h @ w1 (+ gelu -> a1)
    gemm4<0,0,2><<<dim3(4, 256, 1), 128>>>(ph, w1, pz1, KROWS, 512, 128, 128, 512, 512, 0, 0, 0);

    // 7. z2 = a1 @ w2 -> dpred (fused)
    gemm4<0,0,3><<<dim3(1, 256, 1), 128>>>(pa1, w2, pdp, KROWS, 128, 512, 512, 128, 128, 0, 0, 0);

    // 8. dW2 = a1^T @ dpred (batched over 256 chunks)
    gemm4<1,0,0><<<dim3(1, 8, Pn), 128>>>(pa1, pdp, pgw2, 512, 128, 64, 512, 128, 128,
                                          64L * 512, 64L * 128, 512L * 128);

    // 9. dz1 = (dpred @ w2^T) * gelu'(z1)
    gemm4<0,1,4><<<dim3(4, 256, 1), 128>>>(pdp, w2, pdz, KROWS, 512, 128, 128, 128, 512, 0, 0, 0);

    // 10. dW1 = h^T @ dz1 (batched)
    gemm4<1,0,0><<<dim3(4, 2, Pn), 128>>>(ph, pdz, pgw1, 128, 512, 64, 128, 512, 512,
                                          64L * 128, 64L * 512, 128L * 512);

    // 11. dh = dz1 @ w1^T
    gemm4<0,1,0><<<dim3(1, 256, 1), 128>>>(pdz, w1, pdh, KROWS, 128, 512, 512, 512, 128, 0, 0, 0);

    // 12. dg reduction
    dg_kernel<<<Pn, 128>>>();

    // 13. momentum + decay scan, writes per-chunk w_prev
    {
        const int E = DHn + DHn * DHIDn + DHIDn * DHn;
        scan_kernel<<<dim3((E + 255) / 256, BHn), 256>>>(memg, w1, w2);
    }

    // 14. q-row RMS scaled by g_prev
    hq_kernel<<<KROWS, 128>>>();

    // 15. z1r = hq @ w1_prev (batched, gelu -> a1 reuse). M=64 per chunk.
    gemm4<0,0,5><<<dim3(4, 1, Pn), 128>>>(phq, pw1p, pa1, 64, 512, 128, 128, 512, 512,
                                          64L * 128, 128L * 512, 64L * 512);

    // 16. z2r = a1r @ w2_prev -> (.. + q) * gate, token-major
    gemm4<0,0,6><<<dim3(1, 1, Pn), 128>>>(pa1, pw2p, pret, 64, 128, 512, 512, 128, 128,
                                          64L * 512, 512L * 128, 0);

    // 17. combine: out = ret @ Wc
    gemm4<0,0,0><<<dim3(4, 64, 1), 128>>>(pret, Wc, out, ROWS, 512, 512, 512, 512, 512, 0, 0, 0);
}